// round 14
// baseline (speedup 1.0000x reference)
#include <cuda_runtime.h>
#include <cuda_fp16.h>
#include <cstdint>

#define FULL_MASK 0xffffffffu

__device__ __forceinline__ float tanha(float x) {
    float r; asm("tanh.approx.f32 %0, %1;" : "=f"(r) : "f"(x)); return r;
}
// pack two f32 -> f16x2 (hi arg in upper 16 bits, lo arg in lower 16)
__device__ __forceinline__ uint32_t pack_f16(float hi, float lo) {
    uint32_t r; asm("cvt.rn.f16x2.f32 %0, %1, %2;" : "=r"(r) : "f"(hi), "f"(lo));
    return r;
}
__device__ __forceinline__ float f16_round(float v) {
    return __half2float(__float2half_rn(v));
}

// D[16,8] += A[16,16] * B[16,8], f16 in, f32 accum. Row-major A, col-major B.
__device__ __forceinline__ void mma16816(float4& d,
                                         uint32_t a0, uint32_t a1,
                                         uint32_t a2, uint32_t a3,
                                         uint32_t b0, uint32_t b1) {
    asm("mma.sync.aligned.m16n8k16.row.col.f32.f16.f16.f32 "
        "{%0,%1,%2,%3}, {%4,%5,%6,%7}, {%8,%9}, {%0,%1,%2,%3};"
        : "+f"(d.x), "+f"(d.y), "+f"(d.z), "+f"(d.w)
        : "r"(a0), "r"(a1), "r"(a2), "r"(a3), "r"(b0), "r"(b1));
}

// H=32, 4H=128 gates (g-major: n = 32*g + u), I=1, T=512, B=8192.
//
// R14: 12 REAL batches per CTA (grid=683, occupancy 5 CTAs/SM) — M16 rows
// 12-15 are phantom (clamped x, bounded garbage, row-independent in MMA,
// outputs guarded). More co-resident recurrence chains per SMSP for this
// latency-bound kernel; activation scheme reverted to R12 (plain f32 tanh).
//
// CTA (128 thr, 4 warps). Warp w owns unit slice jj = w (units 8jj..8jj+7)
// across ALL 4 gates. M16 rows 0-7 = batches base..+7 (D .x/.y), rows 8-15
// = base+8..+15 (.z/.w). Lane l: gr=l>>2, gc=l&3.
//
// f16 scheme: W_hh prescaled to single f16; h split hi+lo f16 (~22 bits).
// D = Ah*BW + Al*BW per kfrag -> 16 MMAs per warp-step.
// C-init = PS*(x*W_ih + b_ih + b_hh) in fp32.
// Activations: sigmoid(u)=0.5+0.5*tanh(0.5u) (PS folded), tanh via MUFU.
//
// Per-step CTA-wide exchange: each warp publishes its A-word
// (uint4: grp0hi, grp0lo, grp1hi, grp1lo) to a parity ring; after one
// __syncthreads every warp reads all 4 slots back (incl. its own).

#define NBC 12   // real batches per CTA

__global__ void __launch_bounds__(128, 5) lstm_mma_kernel(
    const float* __restrict__ x,      // [B, 512]
    const float* __restrict__ W_ih,   // [128]
    const float* __restrict__ W_hh,   // [128, 32]
    const float* __restrict__ b_ih,   // [128]
    const float* __restrict__ b_hh,   // [128]
    const float* __restrict__ W_lin,  // [32]
    const float* __restrict__ b_lin,  // [1]
    float* __restrict__ out)          // [B]
{
    __shared__ __align__(16) float xs[16][36];      // [row][step] padded
    __shared__ __align__(16) uint4 exch[2][4][32];  // [parity][slot jj][lane]
    __shared__ float psum[4][16];                   // epilogue partials

    const int tid = threadIdx.x;
    const int w   = tid >> 5;      // warp = unit slice jj
    const int l   = tid & 31;
    const int jj  = w;
    const int gr  = l >> 2;
    const int gc  = l & 3;

    // ---- per-warp weight fragments in registers (single f16) ----
    uint2 BW[4][2];                // [gate][kfrag]
    float4 qreg[4];                // (PS*W_ih[m], PS*bias[m], ..[m+1]) per gate
    const int u0 = 8 * jj + 2 * gc;
    #pragma unroll
    for (int g = 0; g < 4; ++g) {
        const float ps = (g == 2) ? 1.0f : 0.5f;
        const int n = 8 * (4 * g + jj) + gr;       // B row for this lane
        const float* wr = W_hh + n * 32;
        #pragma unroll
        for (int kk = 0; kk < 2; ++kk) {
            const int k0 = kk * 16 + 2 * gc;
            BW[g][kk] = make_uint2(
                pack_f16(ps * wr[k0 + 1], ps * wr[k0]),
                pack_f16(ps * wr[k0 + 9], ps * wr[k0 + 8]));
        }
        const int m = 32 * g + u0;                 // gate rows for activations
        qreg[g] = make_float4(ps * W_ih[m],     ps * (b_ih[m]     + b_hh[m]),
                              ps * W_ih[m + 1], ps * (b_ih[m + 1] + b_hh[m + 1]));
    }

    const int base = blockIdx.x * NBC;
    // x staging: thread loads row tid/8 (batch clamped), steps (tid%8)*4..+3
    const int xrow = tid >> 3;
    int xbatch = base + xrow;
    if (xbatch > 8191) xbatch = 8191;              // clamp phantom rows
    const float* xb = x + (size_t)xbatch * 512 + (tid & 7) * 4;
    float* xw = &xs[xrow][(tid & 7) * 4];

    // A-operand words [kfrag][slot] = uint4(grp0hi, grp0lo, grp1hi, grp1lo)
    uint4 Aw[2][2];
    #pragma unroll
    for (int kf = 0; kf < 2; ++kf)
        #pragma unroll
        for (int s = 0; s < 2; ++s) Aw[kf][s] = make_uint4(0u, 0u, 0u, 0u);

    float cc[2][2] = {}, hh[2][2] = {};   // [grp][e]

    for (int t0 = 0; t0 < 512; t0 += 32) {
        const float4 xv = *reinterpret_cast<const float4*>(xb + t0);
        *reinterpret_cast<float4*>(xw) = xv;
        __syncthreads();

        #pragma unroll 2
        for (int tc = 0; tc < 32; ++tc) {
            const int par = tc & 1;
            const float xtA = xs[gr][tc];
            const float xtB = xs[gr + 8][tc];

            float4 d[4];
            #pragma unroll
            for (int g = 0; g < 4; ++g) {
                d[g].x = fmaf(xtA, qreg[g].x, qreg[g].y);
                d[g].y = fmaf(xtA, qreg[g].z, qreg[g].w);
                d[g].z = fmaf(xtB, qreg[g].x, qreg[g].y);
                d[g].w = fmaf(xtB, qreg[g].z, qreg[g].w);
                #pragma unroll
                for (int kf = 0; kf < 2; ++kf) {
                    // Ah*BW + Al*BW for this kfrag
                    mma16816(d[g], Aw[kf][0].x, Aw[kf][0].z,
                                   Aw[kf][1].x, Aw[kf][1].z,
                             BW[g][kf].x, BW[g][kf].y);
                    mma16816(d[g], Aw[kf][0].y, Aw[kf][0].w,
                                   Aw[kf][1].y, Aw[kf][1].w,
                             BW[g][kf].x, BW[g][kf].y);
                }
            }

            // ---- activations: 2 grps x 2 elems (plain f32 tanh, R12) ----
            #pragma unroll
            for (int e = 0; e < 2; ++e) {
                {   // grp 0 (.x/.y)
                    const float pi = e ? d[0].y : d[0].x;
                    const float pf = e ? d[1].y : d[1].x;
                    const float pg = e ? d[2].y : d[2].x;
                    const float po = e ? d[3].y : d[3].x;
                    const float si = fmaf(0.5f, tanha(pi), 0.5f);
                    const float sf = fmaf(0.5f, tanha(pf), 0.5f);
                    const float tg = tanha(pg);
                    const float so = fmaf(0.5f, tanha(po), 0.5f);
                    cc[0][e] = fmaf(sf, cc[0][e], si * tg);
                    hh[0][e] = so * tanha(cc[0][e]);
                }
                {   // grp 1 (.z/.w)
                    const float pi = e ? d[0].w : d[0].z;
                    const float pf = e ? d[1].w : d[1].z;
                    const float pg = e ? d[2].w : d[2].z;
                    const float po = e ? d[3].w : d[3].z;
                    const float si = fmaf(0.5f, tanha(pi), 0.5f);
                    const float sf = fmaf(0.5f, tanha(pf), 0.5f);
                    const float tg = tanha(pg);
                    const float so = fmaf(0.5f, tanha(po), 0.5f);
                    cc[1][e] = fmaf(sf, cc[1][e], si * tg);
                    hh[1][e] = so * tanha(cc[1][e]);
                }
            }

            // publish this warp's A-word: h split hi+lo (f16)
            const float h00h = f16_round(hh[0][0]);
            const float h01h = f16_round(hh[0][1]);
            const float h10h = f16_round(hh[1][0]);
            const float h11h = f16_round(hh[1][1]);
            const uint32_t pa = pack_f16(h01h, h00h);
            const uint32_t la = pack_f16(hh[0][1] - h01h, hh[0][0] - h00h);
            const uint32_t pb = pack_f16(h11h, h10h);
            const uint32_t lb = pack_f16(hh[1][1] - h11h, hh[1][0] - h10h);
            exch[par][jj][l] = make_uint4(pa, la, pb, lb);

            __syncthreads();

            #pragma unroll
            for (int kf = 0; kf < 2; ++kf)
                #pragma unroll
                for (int s = 0; s < 2; ++s)
                    Aw[kf][s] = exch[par][2 * kf + s][l];
        }
    }

    // ---- epilogue: out[b] = dot(h, W_lin) + b_lin ----
    const float wl0 = W_lin[u0], wl1 = W_lin[u0 + 1];
    float vA = fmaf(hh[0][0], wl0, hh[0][1] * wl1);
    float vB = fmaf(hh[1][0], wl0, hh[1][1] * wl1);
    vA += __shfl_xor_sync(FULL_MASK, vA, 1);
    vA += __shfl_xor_sync(FULL_MASK, vA, 2);
    vB += __shfl_xor_sync(FULL_MASK, vB, 1);
    vB += __shfl_xor_sync(FULL_MASK, vB, 2);
    if (gc == 0) {
        psum[jj][gr]     = vA;
        psum[jj][gr + 8] = vB;
    }
    __syncthreads();
    if (w == 0 && l < NBC && base + l < 8192) {
        out[base + l] = psum[0][l] + psum[1][l] + psum[2][l] + psum[3][l]
                        + b_lin[0];
    }
}

extern "C" void kernel_launch(void* const* d_in, const int* in_sizes, int n_in,
                              void* d_out, int out_size) {
    const float* x     = (const float*)d_in[0];
    const float* W_ih  = (const float*)d_in[1];
    const float* W_hh  = (const float*)d_in[2];
    const float* b_ih  = (const float*)d_in[3];
    const float* b_hh  = (const float*)d_in[4];
    const float* W_lin = (const float*)d_in[5];
    const float* b_lin = (const float*)d_in[6];
    float* out = (float*)d_out;

    // ceil(8192 / 12) = 683 CTAs of 128 threads (4 warps), 5 CTAs/SM.
    lstm_mma_kernel<<<683, 128>>>(x, W_ih, W_hh, b_ih, b_hh, W_lin, b_lin, out);
}

// round 15
// speedup vs baseline: 1.5608x; 1.5608x over previous
#include <cuda_runtime.h>
#include <cuda_fp16.h>
#include <cstdint>

#define FULL_MASK 0xffffffffu

__device__ __forceinline__ float tanha(float x) {
    float r; asm("tanh.approx.f32 %0, %1;" : "=f"(r) : "f"(x)); return r;
}
// pack two f32 -> f16x2 (hi arg in upper 16 bits, lo arg in lower 16)
__device__ __forceinline__ uint32_t pack_f16(float hi, float lo) {
    uint32_t r; asm("cvt.rn.f16x2.f32 %0, %1, %2;" : "=r"(r) : "f"(hi), "f"(lo));
    return r;
}

// D[16,8] += A[16,16] * B[16,8], f16 in, f32 accum. Row-major A, col-major B.
__device__ __forceinline__ void mma16816(float4& d,
                                         uint32_t a0, uint32_t a1,
                                         uint32_t a2, uint32_t a3,
                                         uint32_t b0, uint32_t b1) {
    asm("mma.sync.aligned.m16n8k16.row.col.f32.f16.f16.f32 "
        "{%0,%1,%2,%3}, {%4,%5,%6,%7}, {%8,%9}, {%0,%1,%2,%3};"
        : "+f"(d.x), "+f"(d.y), "+f"(d.z), "+f"(d.w)
        : "r"(a0), "r"(a1), "r"(a2), "r"(a3), "r"(b0), "r"(b1));
}

// H=32, 4H=128 gates (g-major: n = 32*g + u), I=1, T=512, B=8192.
//
// R15 = R12 shape with SINGLE-f16 h (no hi/lo split):
//   W_hh prescaled single f16 (measured cost: rel_err 1.07e-6 -> 1.17e-5);
//   h rounded to single f16 per step (same 2^-11 relative perturbation).
//   D = A*BW per kfrag -> 8 MMAs per warp-step (was 16); exchange word
//   shrinks to uint2; publish is just 2 cvt.rn.f16x2 + STS.64.
//
// CTA (128 thr, 4 warps) = 16 batches. Warp w owns unit slice jj = w
// (units 8jj..8jj+7) across ALL 4 gates. M16 rows 0-7 = batches base..+7
// (D .x/.y), rows 8-15 = base+8..+15 (.z/.w). Lane l: gr=l>>2, gc=l&3.
// C-init = PS*(x*W_ih + b_ih + b_hh) in fp32.
// Activations: sigmoid(u)=0.5+0.5*tanh(0.5u) (PS folded), tanh via MUFU.
//
// Per-step CTA-wide exchange: each warp publishes its A-word
// (uint2: grp0, grp1) to a parity ring; after one __syncthreads every
// warp reads all 4 slots back (incl. its own).

__global__ void __launch_bounds__(128, 4) lstm_mma_kernel(
    const float* __restrict__ x,      // [B, 512]
    const float* __restrict__ W_ih,   // [128]
    const float* __restrict__ W_hh,   // [128, 32]
    const float* __restrict__ b_ih,   // [128]
    const float* __restrict__ b_hh,   // [128]
    const float* __restrict__ W_lin,  // [32]
    const float* __restrict__ b_lin,  // [1]
    float* __restrict__ out)          // [B]
{
    __shared__ __align__(16) float xs[16][36];      // [batch][step] padded
    __shared__ __align__(8)  uint2 exch[2][4][32];  // [parity][slot jj][lane]
    __shared__ float psum[4][16];                   // epilogue partials

    const int tid = threadIdx.x;
    const int w   = tid >> 5;      // warp = unit slice jj
    const int l   = tid & 31;
    const int jj  = w;
    const int gr  = l >> 2;
    const int gc  = l & 3;

    // ---- per-warp weight fragments in registers (single f16) ----
    uint2 BW[4][2];                // [gate][kfrag]
    float4 qreg[4];                // (PS*W_ih[m], PS*bias[m], ..[m+1]) per gate
    const int u0 = 8 * jj + 2 * gc;
    #pragma unroll
    for (int g = 0; g < 4; ++g) {
        const float ps = (g == 2) ? 1.0f : 0.5f;
        const int n = 8 * (4 * g + jj) + gr;       // B row for this lane
        const float* wr = W_hh + n * 32;
        #pragma unroll
        for (int kk = 0; kk < 2; ++kk) {
            const int k0 = kk * 16 + 2 * gc;
            BW[g][kk] = make_uint2(
                pack_f16(ps * wr[k0 + 1], ps * wr[k0]),
                pack_f16(ps * wr[k0 + 9], ps * wr[k0 + 8]));
        }
        const int m = 32 * g + u0;                 // gate rows for activations
        qreg[g] = make_float4(ps * W_ih[m],     ps * (b_ih[m]     + b_hh[m]),
                              ps * W_ih[m + 1], ps * (b_ih[m + 1] + b_hh[m + 1]));
    }

    const int base = blockIdx.x * 16;
    // x staging: thread loads batch tid/8, steps (tid%8)*4..+3 per 32-chunk
    const float* xb = x + (size_t)(base + (tid >> 3)) * 512 + (tid & 7) * 4;
    float* xw = &xs[tid >> 3][(tid & 7) * 4];

    // A-operand words [kfrag][slot] = uint2(grp0, grp1)
    uint2 Aw[2][2];
    #pragma unroll
    for (int kf = 0; kf < 2; ++kf)
        #pragma unroll
        for (int s = 0; s < 2; ++s) Aw[kf][s] = make_uint2(0u, 0u);

    float cc[2][2] = {}, hh[2][2] = {};   // [grp][e]

    for (int t0 = 0; t0 < 512; t0 += 32) {
        const float4 xv = *reinterpret_cast<const float4*>(xb + t0);
        *reinterpret_cast<float4*>(xw) = xv;
        __syncthreads();

        #pragma unroll 2
        for (int tc = 0; tc < 32; ++tc) {
            const int par = tc & 1;
            const float xtA = xs[gr][tc];
            const float xtB = xs[gr + 8][tc];

            float4 d[4];
            #pragma unroll
            for (int g = 0; g < 4; ++g) {
                d[g].x = fmaf(xtA, qreg[g].x, qreg[g].y);
                d[g].y = fmaf(xtA, qreg[g].z, qreg[g].w);
                d[g].z = fmaf(xtB, qreg[g].x, qreg[g].y);
                d[g].w = fmaf(xtB, qreg[g].z, qreg[g].w);
                #pragma unroll
                for (int kf = 0; kf < 2; ++kf) {
                    mma16816(d[g], Aw[kf][0].x, Aw[kf][0].y,
                                   Aw[kf][1].x, Aw[kf][1].y,
                             BW[g][kf].x, BW[g][kf].y);
                }
            }

            // ---- activations: 2 grps x 2 elems (plain f32 tanh) ----
            #pragma unroll
            for (int e = 0; e < 2; ++e) {
                {   // grp 0 (.x/.y)
                    const float pi = e ? d[0].y : d[0].x;
                    const float pf = e ? d[1].y : d[1].x;
                    const float pg = e ? d[2].y : d[2].x;
                    const float po = e ? d[3].y : d[3].x;
                    const float si = fmaf(0.5f, tanha(pi), 0.5f);
                    const float sf = fmaf(0.5f, tanha(pf), 0.5f);
                    const float tg = tanha(pg);
                    const float so = fmaf(0.5f, tanha(po), 0.5f);
                    cc[0][e] = fmaf(sf, cc[0][e], si * tg);
                    hh[0][e] = so * tanha(cc[0][e]);
                }
                {   // grp 1 (.z/.w)
                    const float pi = e ? d[0].w : d[0].z;
                    const float pf = e ? d[1].w : d[1].z;
                    const float pg = e ? d[2].w : d[2].z;
                    const float po = e ? d[3].w : d[3].z;
                    const float si = fmaf(0.5f, tanha(pi), 0.5f);
                    const float sf = fmaf(0.5f, tanha(pf), 0.5f);
                    const float tg = tanha(pg);
                    const float so = fmaf(0.5f, tanha(po), 0.5f);
                    cc[1][e] = fmaf(sf, cc[1][e], si * tg);
                    hh[1][e] = so * tanha(cc[1][e]);
                }
            }

            // publish this warp's A-word: single f16 h (cvt does the rounding)
            exch[par][jj][l] = make_uint2(pack_f16(hh[0][1], hh[0][0]),
                                          pack_f16(hh[1][1], hh[1][0]));

            __syncthreads();

            #pragma unroll
            for (int kf = 0; kf < 2; ++kf)
                #pragma unroll
                for (int s = 0; s < 2; ++s)
                    Aw[kf][s] = exch[par][2 * kf + s][l];
        }
    }

    // ---- epilogue: out[b] = dot(h, W_lin) + b_lin ----
    const float wl0 = W_lin[u0], wl1 = W_lin[u0 + 1];
    float vA = fmaf(hh[0][0], wl0, hh[0][1] * wl1);
    float vB = fmaf(hh[1][0], wl0, hh[1][1] * wl1);
    vA += __shfl_xor_sync(FULL_MASK, vA, 1);
    vA += __shfl_xor_sync(FULL_MASK, vA, 2);
    vB += __shfl_xor_sync(FULL_MASK, vB, 1);
    vB += __shfl_xor_sync(FULL_MASK, vB, 2);
    if (gc == 0) {
        psum[jj][gr]     = vA;
        psum[jj][gr + 8] = vB;
    }
    __syncthreads();
    if (w == 0 && l < 16) {
        out[base + l] = psum[0][l] + psum[1][l] + psum[2][l] + psum[3][l]
                        + b_lin[0];
    }
}

extern "C" void kernel_launch(void* const* d_in, const int* in_sizes, int n_in,
                              void* d_out, int out_size) {
    const float* x     = (const float*)d_in[0];
    const float* W_ih  = (const float*)d_in[1];
    const float* W_hh  = (const float*)d_in[2];
    const float* b_ih  = (const float*)d_in[3];
    const float* b_hh  = (const float*)d_in[4];
    const float* W_lin = (const float*)d_in[5];
    const float* b_lin = (const float*)d_in[6];
    float* out = (float*)d_out;

    // 8192 batches / 16 per CTA = 512 CTAs of 128 threads (4 warps).
    lstm_mma_kernel<<<512, 128>>>(x, W_ih, W_hh, b_ih, b_hh, W_lin, b_lin, out);
}